// round 4
// baseline (speedup 1.0000x reference)
#include <cuda_runtime.h>
#include <cuda_bf16.h>
#include <cstdint>

// ---------------------------------------------------------------------------
// Problem constants
// ---------------------------------------------------------------------------
constexpr int Bq = 2, Tq = 2048, Cq = 1024, Hq = 16, Dq = 64;
constexpr int Mrows = Bq * Tq;      // 4096
constexpr int N_QKV = 3 * Cq;       // 3072

// Scratch (device globals — no allocation allowed)
__device__ float g_q[Bq * Hq * Tq * Dq];   // [B,H,T,D] (tf32-rounded)
__device__ float g_k[Bq * Hq * Tq * Dq];
__device__ float g_v[Bq * Hq * Tq * Dq];
__device__ float g_y[Bq * Tq * Cq];        // [B,T,C]  (tf32-rounded)
__device__ float g_xr[Mrows * Cq];         // tf32-rounded x
__device__ float g_wqkv_t[N_QKV * Cq];     // [3C, C]  (Wqkv^T, tf32-rounded)
__device__ float g_wo_t[Cq * Cq];          // [C, C]   (Wo^T, tf32-rounded)

// ---------------------------------------------------------------------------
// Helpers
// ---------------------------------------------------------------------------
__device__ __forceinline__ uint32_t f2tf(float x) {
    uint32_t r;
    asm("cvt.rna.tf32.f32 %0, %1;" : "=r"(r) : "f"(x));
    return r;
}
__device__ __forceinline__ float f2tf_f(float x) { return __uint_as_float(f2tf(x)); }

__device__ __forceinline__ void mma8(float* d, const uint32_t* a, const uint32_t* b) {
    asm volatile(
        "mma.sync.aligned.m16n8k8.row.col.f32.tf32.tf32.f32 "
        "{%0,%1,%2,%3}, {%4,%5,%6,%7}, {%8,%9}, {%0,%1,%2,%3};\n"
        : "+f"(d[0]), "+f"(d[1]), "+f"(d[2]), "+f"(d[3])
        : "r"(a[0]), "r"(a[1]), "r"(a[2]), "r"(a[3]), "r"(b[0]), "r"(b[1]));
}

__device__ __forceinline__ void cpasync16(uint32_t dst, const void* src) {
    asm volatile("cp.async.cg.shared.global [%0], [%1], 16;" :: "r"(dst), "l"(src));
}
#define CP_COMMIT() asm volatile("cp.async.commit_group;" ::: "memory")
#define CP_WAIT1()  asm volatile("cp.async.wait_group 1;" ::: "memory")

// ---------------------------------------------------------------------------
// tf32 rounding copy: dst[i] = tf32(src[i])
// ---------------------------------------------------------------------------
__global__ __launch_bounds__(256) void round_tf32(const float* __restrict__ src,
                                                  float* __restrict__ dst, int n4) {
    int i = blockIdx.x * blockDim.x + threadIdx.x;
    if (i < n4) {
        float4 v = ((const float4*)src)[i];
        v.x = f2tf_f(v.x); v.y = f2tf_f(v.y); v.z = f2tf_f(v.z); v.w = f2tf_f(v.w);
        ((float4*)dst)[i] = v;
    }
}

// ---------------------------------------------------------------------------
// Transpose + tf32 round: src [R, Cn] -> dst [Cn, R]
// ---------------------------------------------------------------------------
__global__ __launch_bounds__(256) void transpose_k(const float* __restrict__ src,
                                                   float* __restrict__ dst,
                                                   int R, int Cn) {
    __shared__ float tile[32][33];
    int c0 = blockIdx.x * 32, r0 = blockIdx.y * 32;
    int x = threadIdx.x, y = threadIdx.y;   // 32 x 8
#pragma unroll
    for (int i = 0; i < 32; i += 8)
        tile[y + i][x] = src[(size_t)(r0 + y + i) * Cn + c0 + x];
    __syncthreads();
#pragma unroll
    for (int i = 0; i < 32; i += 8)
        dst[(size_t)(c0 + y + i) * R + r0 + x] = f2tf_f(tile[x][y + i]);
}

// ---------------------------------------------------------------------------
// tf32 mma.sync GEMM with cp.async 3-stage pipeline.
// D[M,N] = A[M,K] @ BT[N,K]^T ; CTA 128x128, BK=32, 8 warps (2x4).
// Inputs must be pre-rounded to tf32.
// mode 0: scatter into g_q/g_k/g_v (rounded); mode 1: out = D + bias (full fp32)
// ---------------------------------------------------------------------------
constexpr int GST = 36;                        // smem row stride (floats)
constexpr int G_STG = 2 * 128 * GST;           // floats per stage (A then B)
constexpr int GEMM_SMEM = 3 * G_STG * 4;       // 110592 bytes

__global__ void __launch_bounds__(256, 2) gemm_mma(const float* __restrict__ A,
                                                   const float* __restrict__ BT,
                                                   int Ktot, int mode,
                                                   const float* __restrict__ bias,
                                                   float* __restrict__ outp) {
    extern __shared__ float sm[];
    const int tid = threadIdx.x, lane = tid & 31, wid = tid >> 5;
    const int wm = wid >> 2, wn = wid & 3;
    const int m0 = blockIdx.y * 128, n0 = blockIdx.x * 128;

    const int lr = tid >> 1, lc = (tid & 1) * 16;
    const float* gA = A  + (size_t)(m0 + lr) * Ktot + lc;
    const float* gB = BT + (size_t)(n0 + lr) * Ktot + lc;
    const uint32_t sbase = (uint32_t)__cvta_generic_to_shared(sm);
    const uint32_t dApart = (uint32_t)(lr * GST + lc) * 4;

    float d[4][4][4];
#pragma unroll
    for (int mi = 0; mi < 4; mi++)
#pragma unroll
        for (int ni = 0; ni < 4; ni++)
#pragma unroll
            for (int e = 0; e < 4; e++) d[mi][ni][e] = 0.f;

    const int nc = Ktot / 32;

    // prologue: stages 0,1
#pragma unroll
    for (int s = 0; s < 2; s++) {
        uint32_t dA = sbase + (uint32_t)(s * G_STG) * 4 + dApart;
        uint32_t dB = dA + 128 * GST * 4;
        const float* pa = gA + s * 32;
        const float* pb = gB + s * 32;
#pragma unroll
        for (int j = 0; j < 4; j++) {
            cpasync16(dA + j * 16, pa + j * 4);
            cpasync16(dB + j * 16, pb + j * 4);
        }
        CP_COMMIT();
    }

    int st = 0;
    for (int c = 0; c < nc; c++) {
        CP_WAIT1();
        __syncthreads();
        int wst = st + 2; if (wst >= 3) wst -= 3;
        if (c + 2 < nc) {
            uint32_t dA = sbase + (uint32_t)(wst * G_STG) * 4 + dApart;
            uint32_t dB = dA + 128 * GST * 4;
            const float* pa = gA + (c + 2) * 32;
            const float* pb = gB + (c + 2) * 32;
#pragma unroll
            for (int j = 0; j < 4; j++) {
                cpasync16(dA + j * 16, pa + j * 4);
                cpasync16(dB + j * 16, pb + j * 4);
            }
        }
        CP_COMMIT();

        const float* cA = sm + st * G_STG;
        const float* cB = cA + 128 * GST;
#pragma unroll
        for (int ks = 0; ks < 4; ks++) {
            const int kc = ks * 8 + (lane & 3);
            uint32_t a[4][4], b[4][2];
#pragma unroll
            for (int mi = 0; mi < 4; mi++) {
                int r = wm * 64 + mi * 16 + (lane >> 2);
                a[mi][0] = __float_as_uint(cA[r * GST + kc]);
                a[mi][1] = __float_as_uint(cA[(r + 8) * GST + kc]);
                a[mi][2] = __float_as_uint(cA[r * GST + kc + 4]);
                a[mi][3] = __float_as_uint(cA[(r + 8) * GST + kc + 4]);
            }
#pragma unroll
            for (int ni = 0; ni < 4; ni++) {
                int cn = wn * 32 + ni * 8 + (lane >> 2);
                b[ni][0] = __float_as_uint(cB[cn * GST + kc]);
                b[ni][1] = __float_as_uint(cB[cn * GST + kc + 4]);
            }
#pragma unroll
            for (int mi = 0; mi < 4; mi++)
#pragma unroll
                for (int ni = 0; ni < 4; ni++) mma8(d[mi][ni], a[mi], b[ni]);
        }
        st++; if (st >= 3) st -= 3;
    }

    // epilogue
#pragma unroll
    for (int mi = 0; mi < 4; mi++) {
#pragma unroll
        for (int half = 0; half < 2; half++) {
            int m = m0 + wm * 64 + mi * 16 + (lane >> 2) + half * 8;
            int bb = m >> 11, t = m & (Tq - 1);
#pragma unroll
            for (int ni = 0; ni < 4; ni++) {
                int n = n0 + wn * 32 + ni * 8 + 2 * (lane & 3);
                float2 v;
                v.x = d[mi][ni][half * 2 + 0];
                v.y = d[mi][ni][half * 2 + 1];
                if (mode == 0) {
                    v.x = f2tf_f(v.x); v.y = f2tf_f(v.y);
                    int which = n >> 10, cc = n & (Cq - 1);
                    int hh = cc >> 6, dd = cc & 63;
                    float* dst = (which == 0) ? g_q : (which == 1) ? g_k : g_v;
                    *(float2*)(dst + (((size_t)(bb * Hq + hh) * Tq + t) * Dq + dd)) = v;
                } else {
                    v.x += __ldg(bias + n);
                    v.y += __ldg(bias + n + 1);
                    *(float2*)(outp + (size_t)m * Cq + n) = v;
                }
            }
        }
    }
}

// ---------------------------------------------------------------------------
// Warp-MMA flash attention (causal). 128 q-rows/CTA, 8 warps x 16 rows,
// 64-key tiles. Fragment-packed SMEM layouts (float2 LDS, conflict-free).
// pack(d) within 8-group: d = g*8 + j + 4e (j<4,e<2) -> g*8 + 2j + e
// ---------------------------------------------------------------------------
constexpr int FST = 72;                    // smem row stride (floats)
constexpr int F_SK = 0;                    // K packed   [64][FST]
constexpr int F_SV = 64 * FST;             // V^T packed [64][FST]  (sVt[d][pkey])
constexpr int F_SP = 2 * 64 * FST;         // P packed   [128][FST]
constexpr int FLASH_SMEM = (2 * 64 * FST + 128 * FST) * 4;  // 73728 bytes

__global__ void __launch_bounds__(256, 2) flash_mma() {
    extern __shared__ float sm[];
    const int tid = threadIdx.x, lane = tid & 31, wid = tid >> 5;
    const int bh = blockIdx.y;
    const int q0 = (gridDim.x - 1 - blockIdx.x) * 128;   // longest blocks first
    const int bb = bh >> 4, h = bh & 15;

    // Q fragments in registers (x0.125 is exact on tf32 values)
    uint32_t qa[8][4];
    {
        const float* r0p = g_q + ((size_t)bh * Tq + q0 + wid * 16 + (lane >> 2)) * Dq;
        const float* r1p = r0p + 8 * Dq;
#pragma unroll
        for (int ks = 0; ks < 8; ks++) {
            int c = ks * 8 + (lane & 3);
            qa[ks][0] = __float_as_uint(r0p[c] * 0.125f);
            qa[ks][1] = __float_as_uint(r1p[c] * 0.125f);
            qa[ks][2] = __float_as_uint(r0p[c + 4] * 0.125f);
            qa[ks][3] = __float_as_uint(r1p[c + 4] * 0.125f);
        }
    }

    float o[8][4];
#pragma unroll
    for (int ni = 0; ni < 8; ni++)
#pragma unroll
        for (int e = 0; e < 4; e++) o[ni][e] = 0.f;
    float m_a = -1e30f, m_b = -1e30f, l_a = 0.f, l_b = 0.f;
    const int row_a = q0 + wid * 16 + (lane >> 2);
    const int row_b = row_a + 8;

    float* Pr_a = sm + F_SP + (wid * 16 + (lane >> 2)) * FST;
    float* Pr_b = Pr_a + 8 * FST;
    // packed store positions for c-frag cols
    const int cc = 2 * (lane & 3);
    const int p0 = ((cc & 3) << 1) + ((cc >> 2) & 1);   // pack(cc); pack(cc+1)=p0+2
    const int fc2 = (lane & 3) * 2;                     // packed col for frag loads

    for (int j0 = 0; j0 < q0 + 128; j0 += 64) {
        __syncthreads();
        // stage K (d-packed) and V^T (key-packed)
        {
            const int key = tid >> 2;
            const int pkey = (key & ~7) + (key & 3) * 2 + ((key >> 2) & 1);
            const int db = (tid & 3) * 16;
            const float* kp = g_k + ((size_t)bh * Tq + j0 + key) * Dq + db;
            const float* vp = g_v + ((size_t)bh * Tq + j0 + key) * Dq + db;
            float* krow = sm + F_SK + key * FST;
            float* vcol = sm + F_SV + pkey;
#pragma unroll
            for (int g = 0; g < 2; g++) {
                int d0 = db + g * 8;
                float4 lo = *(const float4*)(kp + g * 8);
                float4 hi = *(const float4*)(kp + g * 8 + 4);
                float2* kd = (float2*)(krow + d0);
                kd[0] = make_float2(lo.x, hi.x);
                kd[1] = make_float2(lo.y, hi.y);
                kd[2] = make_float2(lo.z, hi.z);
                kd[3] = make_float2(lo.w, hi.w);
                float4 vlo = *(const float4*)(vp + g * 8);
                float4 vhi = *(const float4*)(vp + g * 8 + 4);
                vcol[(d0 + 0) * FST] = vlo.x; vcol[(d0 + 1) * FST] = vlo.y;
                vcol[(d0 + 2) * FST] = vlo.z; vcol[(d0 + 3) * FST] = vlo.w;
                vcol[(d0 + 4) * FST] = vhi.x; vcol[(d0 + 5) * FST] = vhi.y;
                vcol[(d0 + 6) * FST] = vhi.z; vcol[(d0 + 7) * FST] = vhi.w;
            }
        }
        __syncthreads();

        // S = Q K^T
        float s[8][4];
#pragma unroll
        for (int ni = 0; ni < 8; ni++)
#pragma unroll
            for (int e = 0; e < 4; e++) s[ni][e] = 0.f;
#pragma unroll
        for (int ks = 0; ks < 8; ks++) {
            const int kcp = ks * 8 + fc2;
#pragma unroll
            for (int ni = 0; ni < 8; ni++) {
                float2 kb = *(const float2*)(sm + F_SK + (ni * 8 + (lane >> 2)) * FST + kcp);
                uint32_t b[2] = { __float_as_uint(kb.x), __float_as_uint(kb.y) };
                mma8(s[ni], qa[ks], b);
            }
        }

        // causal mask (diagonal tiles only)
        if (j0 >= q0) {
#pragma unroll
            for (int ni = 0; ni < 8; ni++) {
                int c0 = j0 + ni * 8 + cc;
                if (c0     > row_a) s[ni][0] = -1e30f;
                if (c0 + 1 > row_a) s[ni][1] = -1e30f;
                if (c0     > row_b) s[ni][2] = -1e30f;
                if (c0 + 1 > row_b) s[ni][3] = -1e30f;
            }
        }

        // online softmax
        float ma = -1e30f, mb = -1e30f;
#pragma unroll
        for (int ni = 0; ni < 8; ni++) {
            ma = fmaxf(ma, fmaxf(s[ni][0], s[ni][1]));
            mb = fmaxf(mb, fmaxf(s[ni][2], s[ni][3]));
        }
        ma = fmaxf(ma, __shfl_xor_sync(0xffffffffu, ma, 1));
        ma = fmaxf(ma, __shfl_xor_sync(0xffffffffu, ma, 2));
        mb = fmaxf(mb, __shfl_xor_sync(0xffffffffu, mb, 1));
        mb = fmaxf(mb, __shfl_xor_sync(0xffffffffu, mb, 2));
        float mna = fmaxf(m_a, ma), mnb = fmaxf(m_b, mb);
        float ca = __expf(m_a - mna), cb = __expf(m_b - mnb);
        m_a = mna; m_b = mnb;
        float sa = 0.f, sb = 0.f;
#pragma unroll
        for (int ni = 0; ni < 8; ni++) {
            s[ni][0] = __expf(s[ni][0] - m_a);
            s[ni][1] = __expf(s[ni][1] - m_a);
            sa += s[ni][0] + s[ni][1];
            s[ni][2] = __expf(s[ni][2] - m_b);
            s[ni][3] = __expf(s[ni][3] - m_b);
            sb += s[ni][2] + s[ni][3];
        }
        sa += __shfl_xor_sync(0xffffffffu, sa, 1);
        sa += __shfl_xor_sync(0xffffffffu, sa, 2);
        sb += __shfl_xor_sync(0xffffffffu, sb, 1);
        sb += __shfl_xor_sync(0xffffffffu, sb, 2);
        l_a = l_a * ca + sa;
        l_b = l_b * cb + sb;
#pragma unroll
        for (int ni = 0; ni < 8; ni++) {
            o[ni][0] *= ca; o[ni][1] *= ca;
            o[ni][2] *= cb; o[ni][3] *= cb;
        }

        // write P (tf32, fragment-packed cols)
#pragma unroll
        for (int ni = 0; ni < 8; ni++) {
            Pr_a[ni * 8 + p0]     = f2tf_f(s[ni][0]);
            Pr_a[ni * 8 + p0 + 2] = f2tf_f(s[ni][1]);
            Pr_b[ni * 8 + p0]     = f2tf_f(s[ni][2]);
            Pr_b[ni * 8 + p0 + 2] = f2tf_f(s[ni][3]);
        }
        __syncwarp();

        // O += P V
#pragma unroll
        for (int ks = 0; ks < 8; ks++) {
            const int kcp = ks * 8 + fc2;
            float2 la = *(const float2*)(Pr_a + kcp);
            float2 lb = *(const float2*)(Pr_b + kcp);
            uint32_t pa[4] = { __float_as_uint(la.x), __float_as_uint(lb.x),
                               __float_as_uint(la.y), __float_as_uint(lb.y) };
#pragma unroll
            for (int ni = 0; ni < 8; ni++) {
                float2 vb2 = *(const float2*)(sm + F_SV + (ni * 8 + (lane >> 2)) * FST + kcp);
                uint32_t vb[2] = { __float_as_uint(vb2.x), __float_as_uint(vb2.y) };
                mma8(o[ni], pa, vb);
            }
        }
    }

    // normalize + write to g_y [B,T,C] (tf32-rounded for the next GEMM)
    const float ia = 1.f / l_a, ib = 1.f / l_b;
    float* ya = g_y + ((size_t)(bb * Tq + row_a)) * Cq + h * Dq;
    float* yb = g_y + ((size_t)(bb * Tq + row_b)) * Cq + h * Dq;
#pragma unroll
    for (int ni = 0; ni < 8; ni++) {
        int c = ni * 8 + cc;
        float2 v;
        v.x = f2tf_f(o[ni][0] * ia); v.y = f2tf_f(o[ni][1] * ia);
        *(float2*)(ya + c) = v;
        v.x = f2tf_f(o[ni][2] * ib); v.y = f2tf_f(o[ni][3] * ib);
        *(float2*)(yb + c) = v;
    }
}

// ---------------------------------------------------------------------------
extern "C" void kernel_launch(void* const* d_in, const int* in_sizes, int n_in,
                              void* d_out, int out_size) {
    const float* x    = (const float*)d_in[0];   // [B,T,C]
    const float* Wqkv = (const float*)d_in[1];   // [C,3C]
    const float* Wo   = (const float*)d_in[2];   // [C,C]
    const float* bo   = (const float*)d_in[3];   // [C]
    float* out = (float*)d_out;                  // [B,T,C]

    static bool attr_done = false;
    if (!attr_done) {
        cudaFuncSetAttribute(gemm_mma, cudaFuncAttributeMaxDynamicSharedMemorySize,
                             GEMM_SMEM);
        cudaFuncSetAttribute(flash_mma, cudaFuncAttributeMaxDynamicSharedMemorySize,
                             FLASH_SMEM);
        attr_done = true;
    }

    float* wqkv_t; cudaGetSymbolAddress((void**)&wqkv_t, g_wqkv_t);
    float* wo_t;   cudaGetSymbolAddress((void**)&wo_t,   g_wo_t);
    float* xr;     cudaGetSymbolAddress((void**)&xr,     g_xr);
    float* yptr;   cudaGetSymbolAddress((void**)&yptr,   g_y);

    // Preprocess: tf32-round x; transpose+round weights
    round_tf32<<<(Mrows * Cq / 4 + 255) / 256, 256>>>(x, xr, Mrows * Cq / 4);
    transpose_k<<<dim3(N_QKV / 32, Cq / 32), dim3(32, 8)>>>(Wqkv, wqkv_t, Cq, N_QKV);
    transpose_k<<<dim3(Cq / 32, Cq / 32), dim3(32, 8)>>>(Wo, wo_t, Cq, Cq);

    // QKV projection
    gemm_mma<<<dim3(N_QKV / 128, Mrows / 128), 256, GEMM_SMEM>>>(
        xr, wqkv_t, Cq, 0, nullptr, nullptr);

    // Attention
    flash_mma<<<dim3(Tq / 128, Bq * Hq), 256, FLASH_SMEM>>>();

    // Output projection
    gemm_mma<<<dim3(Cq / 128, Mrows / 128), 256, GEMM_SMEM>>>(
        yptr, wo_t, Cq, 1, bo, out);
}

// round 5
// speedup vs baseline: 1.2895x; 1.2895x over previous
#include <cuda_runtime.h>
#include <cuda_bf16.h>
#include <cstdint>

// ---------------------------------------------------------------------------
// Problem constants
// ---------------------------------------------------------------------------
constexpr int Bq = 2, Tq = 2048, Cq = 1024, Hq = 16, Dq = 64;
constexpr int Mrows = Bq * Tq;      // 4096
constexpr int N_QKV = 3 * Cq;       // 3072

// Scratch (device globals — no allocation allowed)
__device__ float g_q[Bq * Hq * Tq * Dq];   // [B,H,T,D] natural, tf32
__device__ float g_k[Bq * Hq * Tq * Dq];   // [B,H,T,D] PERMUTED rows, tf32
__device__ float g_v[Bq * Hq * Tq * Dq];   // [B,H,T,D] natural, tf32
__device__ float g_y[Bq * Tq * Cq];        // [B,T,C]  PERMUTED rows, tf32
__device__ float g_xr[Mrows * Cq];         // PERMUTED tf32 x
__device__ float g_wqkv_t[N_QKV * Cq];     // [3C, C] Wqkv^T PERMUTED tf32
__device__ float g_wo_t[Cq * Cq];          // [C, C]  Wo^T  PERMUTED tf32

// ---------------------------------------------------------------------------
// Helpers
// ---------------------------------------------------------------------------
__device__ __forceinline__ uint32_t f2tf(float x) {
    uint32_t r;
    asm("cvt.rna.tf32.f32 %0, %1;" : "=r"(r) : "f"(x));
    return r;
}
__device__ __forceinline__ float f2tf_f(float x) { return __uint_as_float(f2tf(x)); }

__device__ __forceinline__ void mma8(float* d, const uint32_t* a, const uint32_t* b) {
    asm volatile(
        "mma.sync.aligned.m16n8k8.row.col.f32.tf32.tf32.f32 "
        "{%0,%1,%2,%3}, {%4,%5,%6,%7}, {%8,%9}, {%0,%1,%2,%3};\n"
        : "+f"(d[0]), "+f"(d[1]), "+f"(d[2]), "+f"(d[3])
        : "r"(a[0]), "r"(a[1]), "r"(a[2]), "r"(a[3]), "r"(b[0]), "r"(b[1]));
}

__device__ __forceinline__ void cpasync16(uint32_t dst, const void* src) {
    asm volatile("cp.async.cg.shared.global [%0], [%1], 16;" :: "r"(dst), "l"(src));
}
#define CP_COMMIT() asm volatile("cp.async.commit_group;" ::: "memory")
#define CP_WAIT1()  asm volatile("cp.async.wait_group 1;" ::: "memory")

// Column permutation + per-row swizzle.
// Within each 32-col window: 8B unit L = 4*((c&31)>>3) + (c&3); pair pos b=(c>>2)&1.
// Physical unit P = L ^ (4*(row&3)).  float2 at unit P holds logical (c, c+4).
__device__ __forceinline__ int permcol(int c, int rm) {
    int w = c >> 5, cw = c & 31;
    int L = ((cw >> 3) << 2) | (cw & 3);
    int b = (cw >> 2) & 1;
    int P = L ^ (rm << 2);
    return w * 32 + P * 2 + b;
}

// ---------------------------------------------------------------------------
// Preprocess: x -> g_xr (tf32, permuted).  One float4 per thread, exact grid.
// ---------------------------------------------------------------------------
__global__ __launch_bounds__(256) void round_perm_x(const float* __restrict__ src,
                                                    float* __restrict__ dst) {
    int i = blockIdx.x * 256 + threadIdx.x;   // total Mrows*Cq/4
    int row = i >> 8;                          // 256 float4 per 1024-col row
    int col = (i & 255) * 4;
    float4 v = ((const float4*)src)[i];
    const int rm = row & 3;
    float* drow = dst + (size_t)row * Cq;
    drow[permcol(col + 0, rm)] = f2tf_f(v.x);
    drow[permcol(col + 1, rm)] = f2tf_f(v.y);
    drow[permcol(col + 2, rm)] = f2tf_f(v.z);
    drow[permcol(col + 3, rm)] = f2tf_f(v.w);
}

// ---------------------------------------------------------------------------
// Transpose + tf32 + permute: src [R, Cn] -> dst [Cn, R] (dst rows permuted)
// ---------------------------------------------------------------------------
__global__ __launch_bounds__(256) void transpose_perm(const float* __restrict__ src,
                                                      float* __restrict__ dst,
                                                      int R, int Cn) {
    __shared__ float tile[32][33];
    int c0 = blockIdx.x * 32, r0 = blockIdx.y * 32;
    int x = threadIdx.x, y = threadIdx.y;   // 32 x 8
#pragma unroll
    for (int i = 0; i < 32; i += 8)
        tile[y + i][x] = src[(size_t)(r0 + y + i) * Cn + c0 + x];
    __syncthreads();
#pragma unroll
    for (int i = 0; i < 32; i += 8) {
        int drow = c0 + y + i;
        dst[(size_t)drow * R + permcol(r0 + x, drow & 3)] = f2tf_f(tile[x][y + i]);
    }
}

// ---------------------------------------------------------------------------
// tf32 mma.sync GEMM, permuted operands, LDS.64 fragment loads,
// cp.async 3-stage pipeline. CTA 128x128, BK=32, 8 warps (2x4).
// mode 0: scatter q/v natural + k permuted (all tf32-rounded)
// mode 1: out = D + bias (full fp32)
// ---------------------------------------------------------------------------
constexpr int G_STG = 8192;                    // floats per stage (A 4096 + B 4096)
constexpr int GEMM_SMEM = 3 * G_STG * 4;       // 98304 bytes

__global__ void __launch_bounds__(256, 2) gemm_mma(const float* __restrict__ A,
                                                   const float* __restrict__ BT,
                                                   int Ktot, int mode,
                                                   const float* __restrict__ bias,
                                                   float* __restrict__ outp) {
    extern __shared__ float sm[];
    const int tid = threadIdx.x, lane = tid & 31, wid = tid >> 5;
    const int wm = wid >> 2, wn = wid & 3;
    const int m0 = blockIdx.y * 128, n0 = blockIdx.x * 128;
    const int lj = lane & 3, lr4 = lane >> 2;
    const int sw = (lr4 & 3) << 2;

    const int lr = tid >> 1, lc = (tid & 1) * 16;
    const float* gA = A  + (size_t)(m0 + lr) * Ktot + lc;
    const float* gB = BT + (size_t)(n0 + lr) * Ktot + lc;
    const uint32_t sbase = (uint32_t)__cvta_generic_to_shared(sm);
    const uint32_t dApart = (uint32_t)(lr * 32 + lc) * 4;

    float d[4][4][4];
#pragma unroll
    for (int mi = 0; mi < 4; mi++)
#pragma unroll
        for (int ni = 0; ni < 4; ni++)
#pragma unroll
            for (int e = 0; e < 4; e++) d[mi][ni][e] = 0.f;

    const int nc = Ktot / 32;

    // prologue: stages 0,1
#pragma unroll
    for (int s = 0; s < 2; s++) {
        uint32_t dA = sbase + (uint32_t)(s * G_STG) * 4 + dApart;
        uint32_t dB = dA + 16384;
        const float* pa = gA + s * 32;
        const float* pb = gB + s * 32;
#pragma unroll
        for (int j = 0; j < 4; j++) {
            cpasync16(dA + j * 16, pa + j * 4);
            cpasync16(dB + j * 16, pb + j * 4);
        }
        CP_COMMIT();
    }

    int st = 0;
    for (int c = 0; c < nc; c++) {
        CP_WAIT1();
        __syncthreads();
        int wst = st + 2; if (wst >= 3) wst -= 3;
        if (c + 2 < nc) {
            uint32_t dA = sbase + (uint32_t)(wst * G_STG) * 4 + dApart;
            uint32_t dB = dA + 16384;
            const float* pa = gA + (c + 2) * 32;
            const float* pb = gB + (c + 2) * 32;
#pragma unroll
            for (int j = 0; j < 4; j++) {
                cpasync16(dA + j * 16, pa + j * 4);
                cpasync16(dB + j * 16, pb + j * 4);
            }
        }
        CP_COMMIT();

        const float2* s2 = (const float2*)(sm + st * G_STG);
#pragma unroll
        for (int ks = 0; ks < 4; ks++) {
            const int P = ((ks << 2) | lj) ^ sw;
            uint32_t a[4][4], b[4][2];
#pragma unroll
            for (int mi = 0; mi < 4; mi++) {
                int r = wm * 64 + mi * 16 + lr4;
                float2 lo = s2[r * 16 + P];
                float2 hi = s2[(r + 8) * 16 + P];
                a[mi][0] = __float_as_uint(lo.x);
                a[mi][1] = __float_as_uint(hi.x);
                a[mi][2] = __float_as_uint(lo.y);
                a[mi][3] = __float_as_uint(hi.y);
            }
#pragma unroll
            for (int ni = 0; ni < 4; ni++) {
                int cn = wn * 32 + ni * 8 + lr4;
                float2 bb = s2[2048 + cn * 16 + P];
                b[ni][0] = __float_as_uint(bb.x);
                b[ni][1] = __float_as_uint(bb.y);
            }
#pragma unroll
            for (int mi = 0; mi < 4; mi++)
#pragma unroll
                for (int ni = 0; ni < 4; ni++) mma8(d[mi][ni], a[mi], b[ni]);
        }
        st++; if (st >= 3) st -= 3;
    }

    // epilogue
#pragma unroll
    for (int mi = 0; mi < 4; mi++) {
#pragma unroll
        for (int half = 0; half < 2; half++) {
            int m = m0 + wm * 64 + mi * 16 + lr4 + half * 8;
            int bb = m >> 11, t = m & (Tq - 1);
            int rm = m & 3;
#pragma unroll
            for (int ni = 0; ni < 4; ni++) {
                int n = n0 + wn * 32 + ni * 8 + 2 * lj;
                float vx = d[mi][ni][half * 2 + 0];
                float vy = d[mi][ni][half * 2 + 1];
                if (mode == 0) {
                    vx = f2tf_f(vx); vy = f2tf_f(vy);
                    int which = n >> 10, cc = n & (Cq - 1);
                    int hh = cc >> 6, dd = cc & 63;
                    float* dst = (which == 0) ? g_q : (which == 1) ? g_k : g_v;
                    float* rowp = dst + ((size_t)(bb * Hq + hh) * Tq + t) * Dq;
                    if (which == 1) {
                        rowp[permcol(dd, rm)]     = vx;
                        rowp[permcol(dd + 1, rm)] = vy;
                    } else {
                        *(float2*)(rowp + dd) = make_float2(vx, vy);
                    }
                } else {
                    vx += __ldg(bias + n);
                    vy += __ldg(bias + n + 1);
                    *(float2*)(outp + (size_t)m * Cq + n) = make_float2(vx, vy);
                }
            }
        }
    }
}

// ---------------------------------------------------------------------------
// Warp-MMA flash attention (causal). 128 q-rows/CTA, 8 warps x 16 rows,
// 64-key tiles, cp.async double-buffered K/V staging.
// K tile: permuted rows (stride 64, swizzled content -> LDS.64 b-frags).
// V tile: natural rows, stride 72 (conflict-free scalar loads).
// P tile: packed cols (round-4 scheme), stride 72 (LDS.64 a-frags).
// ---------------------------------------------------------------------------
constexpr int FK_F = 64 * 64;              // 4096 floats (K stage)
constexpr int FV_F = 64 * 72;              // 4608 floats (V stage)
constexpr int FSTG = FK_F + FV_F;          // 8704 floats
constexpr int F_SP = 2 * FSTG;             // 17408
constexpr int FLASH_SMEM = (F_SP + 128 * 72) * 4;   // 106496 bytes

__global__ void __launch_bounds__(256, 2) flash_mma() {
    extern __shared__ float sm[];
    const int tid = threadIdx.x, lane = tid & 31, wid = tid >> 5;
    const int bh = blockIdx.y;
    const int q0 = (gridDim.x - 1 - blockIdx.x) * 128;   // longest blocks first
    const int bb = bh >> 4, h = bh & 15;
    const int lj = lane & 3, lr4 = lane >> 2;
    const int sw = (lr4 & 3) << 2;
    const uint32_t sbase = (uint32_t)__cvta_generic_to_shared(sm);

    const float* kbase = g_k + (size_t)bh * Tq * Dq;
    const float* vbase = g_v + (size_t)bh * Tq * Dq;

    // Q fragments in registers (x0.125 exact on tf32 values)
    uint32_t qa[8][4];
    {
        const float* r0p = g_q + ((size_t)bh * Tq + q0 + wid * 16 + lr4) * Dq;
        const float* r1p = r0p + 8 * Dq;
#pragma unroll
        for (int ks = 0; ks < 8; ks++) {
            int c = ks * 8 + lj;
            qa[ks][0] = __float_as_uint(r0p[c] * 0.125f);
            qa[ks][1] = __float_as_uint(r1p[c] * 0.125f);
            qa[ks][2] = __float_as_uint(r0p[c + 4] * 0.125f);
            qa[ks][3] = __float_as_uint(r1p[c + 4] * 0.125f);
        }
    }

    float o[8][4];
#pragma unroll
    for (int ni = 0; ni < 8; ni++)
#pragma unroll
        for (int e = 0; e < 4; e++) o[ni][e] = 0.f;
    float m_a = -1e30f, m_b = -1e30f, l_a = 0.f, l_b = 0.f;
    const int row_a = q0 + wid * 16 + lr4;
    const int row_b = row_a + 8;

    float* Pr_a = sm + F_SP + (wid * 16 + lr4) * 72;
    float* Pr_b = Pr_a + 8 * 72;
    const int cc = 2 * lj;
    const int p0 = ((cc & 3) << 1) + ((cc >> 2) & 1);
    const int fc2 = 2 * lj;

    const int ntile = q0 / 64 + 2;

    // staging lambda-ish: thread copies 4 K-chunks + 4 V-chunks (16B each)
    auto issue_tile = [&](int ti) {
        const int stg = ti & 1;
        const uint32_t kdst0 = sbase + (uint32_t)(stg * FSTG) * 4;
        const uint32_t vdst0 = kdst0 + FK_F * 4;
        const int j0 = ti * 64;
#pragma unroll
        for (int u = 0; u < 4; u++) {
            int id = tid + 256 * u;        // 0..1023
            int row = id >> 4, c16 = id & 15;
            cpasync16(kdst0 + row * 256 + c16 * 16,
                      kbase + (size_t)(j0 + row) * Dq + c16 * 4);
            cpasync16(vdst0 + row * 288 + c16 * 16,
                      vbase + (size_t)(j0 + row) * Dq + c16 * 4);
        }
    };

    issue_tile(0);
    CP_COMMIT();

    for (int ti = 0; ti < ntile; ti++) {
        const int j0 = ti * 64;
        __syncthreads();                    // everyone done reading stage (ti+1)&1
        if (ti + 1 < ntile) issue_tile(ti + 1);
        CP_COMMIT();
        CP_WAIT1();
        __syncthreads();                    // stage ti&1 visible to all

        const int stg = ti & 1;
        const float* sK = sm + stg * FSTG;
        const float2* sK2 = (const float2*)sK;
        const float* sV = sK + FK_F;

        // S = Q K^T
        float s[8][4];
#pragma unroll
        for (int ni = 0; ni < 8; ni++)
#pragma unroll
            for (int e = 0; e < 4; e++) s[ni][e] = 0.f;
#pragma unroll
        for (int ks = 0; ks < 8; ks++) {
            const int P = ((((ks & 3) << 2) | lj) ^ sw) + ((ks >> 2) << 4);
#pragma unroll
            for (int ni = 0; ni < 8; ni++) {
                int keyr = ni * 8 + lr4;
                float2 kb = sK2[keyr * 32 + P];
                uint32_t b[2] = { __float_as_uint(kb.x), __float_as_uint(kb.y) };
                mma8(s[ni], qa[ks], b);
            }
        }

        // causal mask (diagonal tiles only)
        if (j0 >= q0) {
#pragma unroll
            for (int ni = 0; ni < 8; ni++) {
                int c0 = j0 + ni * 8 + cc;
                if (c0     > row_a) s[ni][0] = -1e30f;
                if (c0 + 1 > row_a) s[ni][1] = -1e30f;
                if (c0     > row_b) s[ni][2] = -1e30f;
                if (c0 + 1 > row_b) s[ni][3] = -1e30f;
            }
        }

        // online softmax
        float ma = -1e30f, mb = -1e30f;
#pragma unroll
        for (int ni = 0; ni < 8; ni++) {
            ma = fmaxf(ma, fmaxf(s[ni][0], s[ni][1]));
            mb = fmaxf(mb, fmaxf(s[ni][2], s[ni][3]));
        }
        ma = fmaxf(ma, __shfl_xor_sync(0xffffffffu, ma, 1));
        ma = fmaxf(ma, __shfl_xor_sync(0xffffffffu, ma, 2));
        mb = fmaxf(mb, __shfl_xor_sync(0xffffffffu, mb, 1));
        mb = fmaxf(mb, __shfl_xor_sync(0xffffffffu, mb, 2));
        float mna = fmaxf(m_a, ma), mnb = fmaxf(m_b, mb);
        float ca = __expf(m_a - mna), cb = __expf(m_b - mnb);
        m_a = mna; m_b = mnb;
        float sa = 0.f, sb = 0.f;
#pragma unroll
        for (int ni = 0; ni < 8; ni++) {
            s[ni][0] = __expf(s[ni][0] - m_a);
            s[ni][1] = __expf(s[ni][1] - m_a);
            sa += s[ni][0] + s[ni][1];
            s[ni][2] = __expf(s[ni][2] - m_b);
            s[ni][3] = __expf(s[ni][3] - m_b);
            sb += s[ni][2] + s[ni][3];
        }
        sa += __shfl_xor_sync(0xffffffffu, sa, 1);
        sa += __shfl_xor_sync(0xffffffffu, sa, 2);
        sb += __shfl_xor_sync(0xffffffffu, sb, 1);
        sb += __shfl_xor_sync(0xffffffffu, sb, 2);
        l_a = l_a * ca + sa;
        l_b = l_b * cb + sb;
#pragma unroll
        for (int ni = 0; ni < 8; ni++) {
            o[ni][0] *= ca; o[ni][1] *= ca;
            o[ni][2] *= cb; o[ni][3] *= cb;
        }

        // write P (tf32, packed cols)
#pragma unroll
        for (int ni = 0; ni < 8; ni++) {
            Pr_a[ni * 8 + p0]     = f2tf_f(s[ni][0]);
            Pr_a[ni * 8 + p0 + 2] = f2tf_f(s[ni][1]);
            Pr_b[ni * 8 + p0]     = f2tf_f(s[ni][2]);
            Pr_b[ni * 8 + p0 + 2] = f2tf_f(s[ni][3]);
        }
        __syncwarp();

        // O += P V
#pragma unroll
        for (int ks = 0; ks < 8; ks++) {
            const int kcp = ks * 8 + fc2;
            float2 la = *(const float2*)(Pr_a + kcp);
            float2 lb = *(const float2*)(Pr_b + kcp);
            uint32_t pa[4] = { __float_as_uint(la.x), __float_as_uint(lb.x),
                               __float_as_uint(la.y), __float_as_uint(lb.y) };
            const int kc = ks * 8 + lj;
#pragma unroll
            for (int ni = 0; ni < 8; ni++) {
                int dn = ni * 8 + lr4;
                uint32_t vb[2] = { __float_as_uint(sV[kc * 72 + dn]),
                                   __float_as_uint(sV[(kc + 4) * 72 + dn]) };
                mma8(o[ni], pa, vb);
            }
        }
    }

    // normalize + write g_y PERMUTED (tf32) for the proj GEMM
    const float ia = 1.f / l_a, ib = 1.f / l_b;
    float* yra = g_y + (size_t)(bb * Tq + row_a) * Cq;
    float* yrb = g_y + (size_t)(bb * Tq + row_b) * Cq;
    const int rma = row_a & 3, rmb = row_b & 3;
#pragma unroll
    for (int ni = 0; ni < 8; ni++) {
        int cf = h * 64 + ni * 8 + cc;
        yra[permcol(cf, rma)]     = f2tf_f(o[ni][0] * ia);
        yra[permcol(cf + 1, rma)] = f2tf_f(o[ni][1] * ia);
        yrb[permcol(cf, rmb)]     = f2tf_f(o[ni][2] * ib);
        yrb[permcol(cf + 1, rmb)] = f2tf_f(o[ni][3] * ib);
    }
}

// ---------------------------------------------------------------------------
extern "C" void kernel_launch(void* const* d_in, const int* in_sizes, int n_in,
                              void* d_out, int out_size) {
    const float* x    = (const float*)d_in[0];   // [B,T,C]
    const float* Wqkv = (const float*)d_in[1];   // [C,3C]
    const float* Wo   = (const float*)d_in[2];   // [C,C]
    const float* bo   = (const float*)d_in[3];   // [C]
    float* out = (float*)d_out;                  // [B,T,C]

    static bool attr_done = false;
    if (!attr_done) {
        cudaFuncSetAttribute(gemm_mma, cudaFuncAttributeMaxDynamicSharedMemorySize,
                             GEMM_SMEM);
        cudaFuncSetAttribute(flash_mma, cudaFuncAttributeMaxDynamicSharedMemorySize,
                             FLASH_SMEM);
        attr_done = true;
    }

    float* wqkv_t; cudaGetSymbolAddress((void**)&wqkv_t, g_wqkv_t);
    float* wo_t;   cudaGetSymbolAddress((void**)&wo_t,   g_wo_t);
    float* xr;     cudaGetSymbolAddress((void**)&xr,     g_xr);
    float* yptr;   cudaGetSymbolAddress((void**)&yptr,   g_y);

    // Preprocess: tf32+permute x; transpose+tf32+permute weights
    round_perm_x<<<Mrows * Cq / 4 / 256, 256>>>(x, xr);
    transpose_perm<<<dim3(N_QKV / 32, Cq / 32), dim3(32, 8)>>>(Wqkv, wqkv_t, Cq, N_QKV);
    transpose_perm<<<dim3(Cq / 32, Cq / 32), dim3(32, 8)>>>(Wo, wo_t, Cq, Cq);

    // QKV projection
    gemm_mma<<<dim3(N_QKV / 128, Mrows / 128), 256, GEMM_SMEM>>>(
        xr, wqkv_t, Cq, 0, nullptr, nullptr);

    // Attention
    flash_mma<<<dim3(Tq / 128, Bq * Hq), 256, FLASH_SMEM>>>();

    // Output projection
    gemm_mma<<<dim3(Cq / 128, Mrows / 128), 256, GEMM_SMEM>>>(
        yptr, wo_t, Cq, 1, bo, out);
}

// round 6
// speedup vs baseline: 2.5796x; 2.0005x over previous
#include <cuda_runtime.h>
#include <cuda_fp16.h>
#include <cstdint>

// ---------------------------------------------------------------------------
// Problem constants
// ---------------------------------------------------------------------------
constexpr int Bq = 2, Tq = 2048, Cq = 1024, Hq = 16, Dq = 64;
constexpr int Mrows = Bq * Tq;      // 4096
constexpr int N_QKV = 3 * Cq;       // 3072

// Scratch (device globals — no allocation allowed). All fp16 operands.
__device__ __half g_q[Bq * Hq * Tq * Dq];   // [B,H,T,D]
__device__ __half g_k[Bq * Hq * Tq * Dq];   // [B,H,T,D]
__device__ __half g_v[Bq * Hq * Tq * Dq];   // [B,H,T,D]
__device__ __half g_y[Bq * Tq * Cq];        // [B,T,C]
__device__ __half g_xr[Mrows * Cq];         // x in fp16
__device__ __half g_wqkv_t[N_QKV * Cq];     // Wqkv^T  [3C, C]
__device__ __half g_wo_t[Cq * Cq];          // Wo^T    [C, C]

// ---------------------------------------------------------------------------
// Helpers
// ---------------------------------------------------------------------------
__device__ __forceinline__ void mma16(float* d, const uint32_t* a, const uint32_t* b) {
    asm volatile(
        "mma.sync.aligned.m16n8k16.row.col.f32.f16.f16.f32 "
        "{%0,%1,%2,%3}, {%4,%5,%6,%7}, {%8,%9}, {%0,%1,%2,%3};\n"
        : "+f"(d[0]), "+f"(d[1]), "+f"(d[2]), "+f"(d[3])
        : "r"(a[0]), "r"(a[1]), "r"(a[2]), "r"(a[3]), "r"(b[0]), "r"(b[1]));
}

#define LDM_X4(r0, r1, r2, r3, addr) \
    asm volatile("ldmatrix.sync.aligned.m8n8.x4.shared.b16 {%0,%1,%2,%3}, [%4];" \
        : "=r"(r0), "=r"(r1), "=r"(r2), "=r"(r3) : "r"(addr))

#define LDM_X4_T(r0, r1, r2, r3, addr) \
    asm volatile("ldmatrix.sync.aligned.m8n8.x4.trans.shared.b16 {%0,%1,%2,%3}, [%4];" \
        : "=r"(r0), "=r"(r1), "=r"(r2), "=r"(r3) : "r"(addr))

__device__ __forceinline__ void cpasync16(uint32_t dst, const void* src) {
    asm volatile("cp.async.cg.shared.global [%0], [%1], 16;" :: "r"(dst), "l"(src));
}
#define CP_COMMIT() asm volatile("cp.async.commit_group;" ::: "memory")
#define CP_WAIT1()  asm volatile("cp.async.wait_group 1;" ::: "memory")

__device__ __forceinline__ uint32_t pack_h2(float x, float y) {
    __half2 h = __float22half2_rn(make_float2(x, y));
    return *(uint32_t*)&h;
}

// ---------------------------------------------------------------------------
// Preprocess: fp32 -> fp16 copy (4 elems/thread)
// ---------------------------------------------------------------------------
__global__ __launch_bounds__(256) void round_h(const float* __restrict__ src,
                                               __half* __restrict__ dst) {
    int i = blockIdx.x * 256 + threadIdx.x;
    float4 v = ((const float4*)src)[i];
    uint2 o;
    o.x = pack_h2(v.x, v.y);
    o.y = pack_h2(v.z, v.w);
    ((uint2*)dst)[i] = o;
}

// Transpose + fp16: src [R, Cn] fp32 -> dst [Cn, R] fp16
__global__ __launch_bounds__(256) void transpose_h(const float* __restrict__ src,
                                                   __half* __restrict__ dst,
                                                   int R, int Cn) {
    __shared__ float tile[32][33];
    int c0 = blockIdx.x * 32, r0 = blockIdx.y * 32;
    int x = threadIdx.x, y = threadIdx.y;   // 32 x 8
#pragma unroll
    for (int i = 0; i < 32; i += 8)
        tile[y + i][x] = src[(size_t)(r0 + y + i) * Cn + c0 + x];
    __syncthreads();
#pragma unroll
    for (int i = 0; i < 32; i += 8)
        dst[(size_t)(c0 + y + i) * R + r0 + x] = __float2half_rn(tile[x][y + i]);
}

// ---------------------------------------------------------------------------
// fp16 mma.sync GEMM: D[M,N] = A[M,K] @ BT[N,K]^T ; fp32 accumulate.
// CTA 128x128, BK=64, 8 warps (2x4, warp tile 64x32), 3-stage cp.async.
// SMEM tile rows are 128B (64 halves), unit-swizzled: phys_u = u ^ (row&7).
// mode 0: epilogue -> g_q/g_k/g_v fp16 [B,H,T,D]; mode 1: out fp32 = D + bias
// ---------------------------------------------------------------------------
constexpr int G_STG_B = 32768;                // bytes/stage: A 16KB + B 16KB
constexpr int GEMM_SMEM = 3 * G_STG_B;        // 98304

__global__ void __launch_bounds__(256, 2) gemm_mma(const __half* __restrict__ A,
                                                   const __half* __restrict__ BT,
                                                   int Ktot, int mode,
                                                   const float* __restrict__ bias,
                                                   float* __restrict__ outp) {
    extern __shared__ char smc[];
    const int tid = threadIdx.x, lane = tid & 31, wid = tid >> 5;
    const int wm = wid >> 2, wn = wid & 3;
    const int m0 = blockIdx.y * 128, n0 = blockIdx.x * 128;
    const int lj = lane & 3, lr4 = lane >> 2;
    const uint32_t sbase = (uint32_t)__cvta_generic_to_shared(smc);

    // cp.async mapping: row = tid>>1 (0..127), units (tid&1)*4 .. +3
    const int crow = tid >> 1, cu0 = (tid & 1) * 4;
    const __half* gA = A  + (size_t)(m0 + crow) * Ktot + cu0 * 8;
    const __half* gB = BT + (size_t)(n0 + crow) * Ktot + cu0 * 8;
    const uint32_t crow_off = crow * 128;
    const int crlow = crow & 7;

    // ldmatrix lane addressing
    const int a_row = wm * 64 + ((lane >> 3) & 1) * 8 + (lane & 7);  // + mi*16
    const int a_hi = lane >> 4;                                       // col-unit +
    const int b_row = wn * 32 + ((lane >> 4) & 1) * 8 + (lane & 7);  // + p*16
    const int b_hi = (lane >> 3) & 1;

    float d[4][4][4];
#pragma unroll
    for (int mi = 0; mi < 4; mi++)
#pragma unroll
        for (int ni = 0; ni < 4; ni++)
#pragma unroll
            for (int e = 0; e < 4; e++) d[mi][ni][e] = 0.f;

    const int nc = Ktot / 64;

    auto stage_copy = [&](int c, int stg) {
        uint32_t base = sbase + stg * G_STG_B;
        const __half* pa = gA + c * 64;
        const __half* pb = gB + c * 64;
#pragma unroll
        for (int j = 0; j < 4; j++) {
            int u = cu0 + j;
            uint32_t phys = (uint32_t)((u ^ crlow) * 16);
            cpasync16(base + crow_off + phys, pa + j * 8);
            cpasync16(base + 16384 + crow_off + phys, pb + j * 8);
        }
    };

    stage_copy(0, 0); CP_COMMIT();
    stage_copy(1, 1); CP_COMMIT();

    int st = 0;
    for (int c = 0; c < nc; c++) {
        CP_WAIT1();
        __syncthreads();
        int wst = st + 2; if (wst >= 3) wst -= 3;
        if (c + 2 < nc) stage_copy(c + 2, wst);
        CP_COMMIT();

        const uint32_t abase = sbase + st * G_STG_B;
        const uint32_t bbase = abase + 16384;
#pragma unroll
        for (int ks = 0; ks < 4; ks++) {
            uint32_t a[4][4], b[4][2];
#pragma unroll
            for (int mi = 0; mi < 4; mi++) {
                int row = a_row + mi * 16;
                uint32_t addr = abase + row * 128 + (((ks * 2 + a_hi) ^ (row & 7)) * 16);
                LDM_X4(a[mi][0], a[mi][1], a[mi][2], a[mi][3], addr);
            }
#pragma unroll
            for (int p = 0; p < 2; p++) {
                int row = b_row + p * 16;
                uint32_t addr = bbase + row * 128 + (((ks * 2 + b_hi) ^ (row & 7)) * 16);
                LDM_X4(b[2 * p][0], b[2 * p][1], b[2 * p + 1][0], b[2 * p + 1][1], addr);
            }
#pragma unroll
            for (int mi = 0; mi < 4; mi++)
#pragma unroll
                for (int ni = 0; ni < 4; ni++) mma16(d[mi][ni], a[mi], b[ni]);
        }
        st++; if (st >= 3) st -= 3;
    }

    // epilogue
#pragma unroll
    for (int mi = 0; mi < 4; mi++) {
#pragma unroll
        for (int half = 0; half < 2; half++) {
            int m = m0 + wm * 64 + mi * 16 + lr4 + half * 8;
            int bb = m >> 11, t = m & (Tq - 1);
#pragma unroll
            for (int ni = 0; ni < 4; ni++) {
                int n = n0 + wn * 32 + ni * 8 + 2 * lj;
                float vx = d[mi][ni][half * 2 + 0];
                float vy = d[mi][ni][half * 2 + 1];
                if (mode == 0) {
                    int which = n >> 10, cc = n & (Cq - 1);
                    int hh = cc >> 6, dd = cc & 63;
                    __half* dst = (which == 0) ? g_q : (which == 1) ? g_k : g_v;
                    uint32_t hv = pack_h2(vx, vy);
                    *(uint32_t*)(dst + ((size_t)(bb * Hq + hh) * Tq + t) * Dq + dd) = hv;
                } else {
                    vx += __ldg(bias + n);
                    vy += __ldg(bias + n + 1);
                    *(float2*)(outp + (size_t)m * Cq + n) = make_float2(vx, vy);
                }
            }
        }
    }
}

// ---------------------------------------------------------------------------
// fp16 warp-MMA flash attention (causal). 128 q-rows/CTA, 8 warps x 16 rows,
// 64-key tiles, cp.async double-buffered K/V stages ([64][64]h, swizzled).
// S c-frag reused directly as P a-frag (no SMEM round trip).
// V b-frags via ldmatrix.x4.trans on natural [key][d] rows.
// ---------------------------------------------------------------------------
constexpr int FSTG_B = 16384;              // K 8KB + V 8KB
constexpr int FLASH_SMEM = 2 * FSTG_B;     // 32768

__global__ void __launch_bounds__(256, 2) flash_mma() {
    extern __shared__ char smc[];
    const int tid = threadIdx.x, lane = tid & 31, wid = tid >> 5;
    const int bh = blockIdx.y;
    const int q0 = (gridDim.x - 1 - blockIdx.x) * 128;   // longest blocks first
    const int bb = bh >> 4, h = bh & 15;
    const int lj = lane & 3, lr4 = lane >> 2;
    const uint32_t sbase = (uint32_t)__cvta_generic_to_shared(smc);

    const __half* kbase = g_k + (size_t)bh * Tq * Dq;
    const __half* vbase = g_v + (size_t)bh * Tq * Dq;

    // Q fragments (scale 0.125 folded; exact power of two)
    uint32_t qa[4][4];
    {
        const __half2 sc = __float2half2_rn(0.125f);
        const __half* r0p = g_q + ((size_t)bh * Tq + q0 + wid * 16 + lr4) * Dq;
        const __half* r1p = r0p + 8 * Dq;
#pragma unroll
        for (int ks = 0; ks < 4; ks++) {
            int c = ks * 16 + 2 * lj;
            __half2 v0 = __hmul2(*(const __half2*)(r0p + c), sc);
            __half2 v1 = __hmul2(*(const __half2*)(r1p + c), sc);
            __half2 v2 = __hmul2(*(const __half2*)(r0p + c + 8), sc);
            __half2 v3 = __hmul2(*(const __half2*)(r1p + c + 8), sc);
            qa[ks][0] = *(uint32_t*)&v0; qa[ks][1] = *(uint32_t*)&v1;
            qa[ks][2] = *(uint32_t*)&v2; qa[ks][3] = *(uint32_t*)&v3;
        }
    }

    float o[8][4];
#pragma unroll
    for (int ni = 0; ni < 8; ni++)
#pragma unroll
        for (int e = 0; e < 4; e++) o[ni][e] = 0.f;
    float m_a = -1e30f, m_b = -1e30f, l_a = 0.f, l_b = 0.f;
    const int row_a = q0 + wid * 16 + lr4;
    const int row_b = row_a + 8;
    const int cc = 2 * lj;

    // ldmatrix lane addressing (K: rows=keys; V: rows=keys, trans)
    const int k_row = ((lane >> 4) & 1) * 8 + (lane & 7);   // + p*16
    const int k_hi = (lane >> 3) & 1;
    const int v_row = ((lane >> 3) & 1) * 8 + (lane & 7);   // + ks*16
    const int v_hi = lane >> 4;

    const int ntile = q0 / 64 + 2;

    // staging: K rows [64][64]h + V rows [64][64]h, swizzled units
    auto issue_tile = [&](int ti) {
        const uint32_t kd = sbase + (ti & 1) * FSTG_B;
        const uint32_t vd = kd + 8192;
        const int j0 = ti * 64;
#pragma unroll
        for (int s = 0; s < 2; s++) {
            int id = tid + 256 * s;           // 0..511
            int row = id >> 3, u = id & 7;
            uint32_t off = row * 128 + ((u ^ (row & 7)) * 16);
            cpasync16(kd + off, kbase + (size_t)(j0 + row) * Dq + u * 8);
            cpasync16(vd + off, vbase + (size_t)(j0 + row) * Dq + u * 8);
        }
    };

    issue_tile(0);
    CP_COMMIT();

    for (int ti = 0; ti < ntile; ti++) {
        const int j0 = ti * 64;
        __syncthreads();
        if (ti + 1 < ntile) issue_tile(ti + 1);
        CP_COMMIT();
        CP_WAIT1();
        __syncthreads();

        const uint32_t kstg = sbase + (ti & 1) * FSTG_B;
        const uint32_t vstg = kstg + 8192;

        // S = Q K^T
        float s[8][4];
#pragma unroll
        for (int ni = 0; ni < 8; ni++)
#pragma unroll
            for (int e = 0; e < 4; e++) s[ni][e] = 0.f;
#pragma unroll
        for (int ks = 0; ks < 4; ks++) {
#pragma unroll
            for (int p = 0; p < 4; p++) {
                int row = k_row + p * 16;
                uint32_t addr = kstg + row * 128 + (((ks * 2 + k_hi) ^ (row & 7)) * 16);
                uint32_t b0, b1, b2, b3;
                LDM_X4(b0, b1, b2, b3, addr);
                uint32_t bA[2] = { b0, b1 }, bB[2] = { b2, b3 };
                mma16(s[2 * p], qa[ks], bA);
                mma16(s[2 * p + 1], qa[ks], bB);
            }
        }

        // causal mask (diagonal tiles only)
        if (j0 >= q0) {
#pragma unroll
            for (int ni = 0; ni < 8; ni++) {
                int c0 = j0 + ni * 8 + cc;
                if (c0     > row_a) s[ni][0] = -1e30f;
                if (c0 + 1 > row_a) s[ni][1] = -1e30f;
                if (c0     > row_b) s[ni][2] = -1e30f;
                if (c0 + 1 > row_b) s[ni][3] = -1e30f;
            }
        }

        // online softmax (fp32)
        float ma = -1e30f, mb = -1e30f;
#pragma unroll
        for (int ni = 0; ni < 8; ni++) {
            ma = fmaxf(ma, fmaxf(s[ni][0], s[ni][1]));
            mb = fmaxf(mb, fmaxf(s[ni][2], s[ni][3]));
        }
        ma = fmaxf(ma, __shfl_xor_sync(0xffffffffu, ma, 1));
        ma = fmaxf(ma, __shfl_xor_sync(0xffffffffu, ma, 2));
        mb = fmaxf(mb, __shfl_xor_sync(0xffffffffu, mb, 1));
        mb = fmaxf(mb, __shfl_xor_sync(0xffffffffu, mb, 2));
        float mna = fmaxf(m_a, ma), mnb = fmaxf(m_b, mb);
        float ca = __expf(m_a - mna), cb = __expf(m_b - mnb);
        m_a = mna; m_b = mnb;
        float sa = 0.f, sb = 0.f;
#pragma unroll
        for (int ni = 0; ni < 8; ni++) {
            s[ni][0] = __expf(s[ni][0] - m_a);
            s[ni][1] = __expf(s[ni][1] - m_a);
            sa += s[ni][0] + s[ni][1];
            s[ni][2] = __expf(s[ni][2] - m_b);
            s[ni][3] = __expf(s[ni][3] - m_b);
            sb += s[ni][2] + s[ni][3];
        }
        sa += __shfl_xor_sync(0xffffffffu, sa, 1);
        sa += __shfl_xor_sync(0xffffffffu, sa, 2);
        sb += __shfl_xor_sync(0xffffffffu, sb, 1);
        sb += __shfl_xor_sync(0xffffffffu, sb, 2);
        l_a = l_a * ca + sa;
        l_b = l_b * cb + sb;
#pragma unroll
        for (int ni = 0; ni < 8; ni++) {
            o[ni][0] *= ca; o[ni][1] *= ca;
            o[ni][2] *= cb; o[ni][3] *= cb;
        }

        // O += P V  (P fragments direct from S registers)
#pragma unroll
        for (int ks = 0; ks < 4; ks++) {
            uint32_t pa[4];
            pa[0] = pack_h2(s[2 * ks][0], s[2 * ks][1]);
            pa[1] = pack_h2(s[2 * ks][2], s[2 * ks][3]);
            pa[2] = pack_h2(s[2 * ks + 1][0], s[2 * ks + 1][1]);
            pa[3] = pack_h2(s[2 * ks + 1][2], s[2 * ks + 1][3]);
            int row = v_row + ks * 16;
            uint32_t rowoff = vstg + row * 128;
            int rlow = row & 7;
#pragma unroll
            for (int p = 0; p < 4; p++) {
                uint32_t addr = rowoff + (((2 * p + v_hi) ^ rlow) * 16);
                uint32_t b0, b1, b2, b3;
                LDM_X4_T(b0, b1, b2, b3, addr);
                uint32_t bA[2] = { b0, b1 }, bB[2] = { b2, b3 };
                mma16(o[2 * p], pa, bA);
                mma16(o[2 * p + 1], pa, bB);
            }
        }
    }

    // normalize + write g_y fp16 [B,T,C]
    const float ia = 1.f / l_a, ib = 1.f / l_b;
    __half* yra = g_y + (size_t)(bb * Tq + row_a) * Cq + h * Dq;
    __half* yrb = g_y + (size_t)(bb * Tq + row_b) * Cq + h * Dq;
#pragma unroll
    for (int ni = 0; ni < 8; ni++) {
        int cf = ni * 8 + cc;
        *(uint32_t*)(yra + cf) = pack_h2(o[ni][0] * ia, o[ni][1] * ia);
        *(uint32_t*)(yrb + cf) = pack_h2(o[ni][2] * ib, o[ni][3] * ib);
    }
}

// ---------------------------------------------------------------------------
extern "C" void kernel_launch(void* const* d_in, const int* in_sizes, int n_in,
                              void* d_out, int out_size) {
    const float* x    = (const float*)d_in[0];   // [B,T,C]
    const float* Wqkv = (const float*)d_in[1];   // [C,3C]
    const float* Wo   = (const float*)d_in[2];   // [C,C]
    const float* bo   = (const float*)d_in[3];   // [C]
    float* out = (float*)d_out;                  // [B,T,C]

    static bool attr_done = false;
    if (!attr_done) {
        cudaFuncSetAttribute(gemm_mma, cudaFuncAttributeMaxDynamicSharedMemorySize,
                             GEMM_SMEM);
        attr_done = true;
    }

    __half* wqkv_t; cudaGetSymbolAddress((void**)&wqkv_t, g_wqkv_t);
    __half* wo_t;   cudaGetSymbolAddress((void**)&wo_t,   g_wo_t);
    __half* xr;     cudaGetSymbolAddress((void**)&xr,     g_xr);
    __half* yptr;   cudaGetSymbolAddress((void**)&yptr,   g_y);

    // Preprocess: fp16 round x; transpose+fp16 weights
    round_h<<<Mrows * Cq / 4 / 256, 256>>>(x, xr);
    transpose_h<<<dim3(N_QKV / 32, Cq / 32), dim3(32, 8)>>>(Wqkv, wqkv_t, Cq, N_QKV);
    transpose_h<<<dim3(Cq / 32, Cq / 32), dim3(32, 8)>>>(Wo, wo_t, Cq, Cq);

    // QKV projection
    gemm_mma<<<dim3(N_QKV / 128, Mrows / 128), 256, GEMM_SMEM>>>(
        xr, wqkv_t, Cq, 0, nullptr, nullptr);

    // Attention
    flash_mma<<<dim3(Tq / 128, Bq * Hq), 256, FLASH_SMEM>>>();

    // Output projection
    gemm_mma<<<dim3(Cq / 128, Mrows / 128), 256, GEMM_SMEM>>>(
        yptr, wo_t, Cq, 1, bo, out);
}